// round 15
// baseline (speedup 1.0000x reference)
#include <cuda_runtime.h>
#include <math.h>

// Problem constants
#define NPIX   65536        // B*H*W = 16*64*64
#define HW     4096         // 64*64
#define TILE   64           // pixels per block (halved for wave packing)
#define NBLK   (NPIX/TILE)  // 1024
#define NTHR   128          // TILE*2 groups / 1 thread each
#define NTAIL  256          // tail blocks (one per 4 codebook slots)

// Transposed table layout: sT[row*RS + g*GOFF + pix]
//   RS = 164: mod 32 = 4 (bank(row)=4*row), /4 = 41 odd; 16B-aligned rows
//   GOFF = 80: mod 32 = 16 -> phase-1 STS conflict-free
#define RS    164
#define GOFF  80
#define SRED_OFF (48 * RS)       // 7872
#define SMEM_FLOATS (SRED_OFF + 64)

// Output layout (flattened tuple, float32):
// zq[16,18,64,64] | loss | cb_entropy | indices[16,64,64] | group_indices[16,64,64,2] | avg_prob[2,512]
#define OFF_ZQ    0
#define OFF_LOSS  1179648
#define OFF_CBE   1179649
#define OFF_IDX   1179650
#define OFF_GIDX  1245186
#define OFF_AVGP  1376258   // byte addr mod 16 == 8 -> max 8B-wide stores here!

// Deterministic per-block partials; fixed-order reduction trees throughout.
__device__ __align__(16) float g_pavg[NBLK * 1024];
__device__ __align__(16) float g_red[1024];
__device__ float g_pcommit[NBLK];
__device__ float g_pent[NBLK];
__device__ int   g_cnt;          // zero-init; self-resetting each launch

__device__ __forceinline__ void fma2(unsigned long long& acc,
                                     unsigned long long a, unsigned long long b) {
    asm("fma.rn.f32x2 %0, %1, %2, %0;" : "+l"(acc) : "l"(a), "l"(b));
}
__device__ __forceinline__ float hsum2(unsigned long long acc) {
    float lo, hi;
    asm("mov.b64 {%0, %1}, %2;" : "=f"(lo), "=f"(hi) : "l"(acc));
    return lo + hi;
}

__global__ void __launch_bounds__(NTHR) bsq_main(const float* __restrict__ z,
                                                 float* __restrict__ out) {
    extern __shared__ float sT[];
    float* sRed = sT + SRED_OFF;

    const int t   = threadIdx.x;
    const int blk = blockIdx.x;
    const int pix = t >> 1;                  // 0..63
    const int g   = t & 1;                   // group 0/1
    const int P   = blk * TILE + pix;        // global pixel
    const int b   = P >> 12;                 // batch
    const int hw  = P & 4095;

    const float* zp  = z   + (size_t)(b * 18 + g * 9) * HW + hw;
    float*       zqp = out + OFF_ZQ + (size_t)(b * 18 + g * 9) * HW + hw;

    // ---- Phase 1: per-(pixel,group) work ----
    // ent = ln( prod_j (1+E_j) ) + sum_j q_j*a_j,  E=e^{-4|v|}, q=E/(1+E)
    float p[9];
    unsigned gidx = 0;
    float commit = 0.f, qa = 0.f, prodE = 1.f;
#pragma unroll
    for (int j = 0; j < 9; j++) {
        float v = zp[j * HW];
        bool s = v > 0.f;
        gidx = (gidx << 1) | (unsigned)s;
        float zh = s ? 1.f : -1.f;
        zqp[j * HW] = zh;                    // zq forward value == sign(z)
        float d = zh - v;
        commit += d * d;
        float a = 4.f * fabsf(v);
        float E = __expf(-a);
        float onepE = 1.f + E;
        float r = __fdividef(1.f, onepE);
        float q = E * r;
        p[j] = s ? r : q;                    // sigmoid(4v)
        qa += q * a;
        prodE *= onepE;
    }
    float ent = __logf(prodE) + qa;

    // indices: pair of threads (g=0,g=1) are adjacent lanes
    unsigned other = __shfl_xor_sync(0xffffffffu, gidx, 1);
    out[OFF_GIDX + (size_t)P * 2 + g] = (float)gidx;
    if (g == 0)
        out[OFF_IDX + P] = (float)(gidx * 512u + other);

    // build hi[16]/lo[32] in regs, write transposed (conflict-free STS)
    const int col = g * GOFF + pix;
    {
        float hi[16];
        hi[0] = 1.f - p[0]; hi[1] = p[0];
#pragma unroll
        for (int c = 1; c < 4; c++) {
            const int n = 1 << c;
#pragma unroll
            for (int i = n - 1; i >= 0; i--) {
                float v = hi[i];
                hi[2 * i + 1] = v * p[c];
                hi[2 * i]     = v * (1.f - p[c]);
            }
        }
#pragma unroll
        for (int i = 0; i < 16; i++) sT[i * RS + col] = hi[i];
    }
    {
        float lo[32];
        lo[0] = 1.f - p[4]; lo[1] = p[4];
#pragma unroll
        for (int c = 1; c < 5; c++) {
            const int n = 1 << c;
#pragma unroll
            for (int i = n - 1; i >= 0; i--) {
                float v = lo[i];
                lo[2 * i + 1] = v * p[4 + c];
                lo[2 * i]     = v * (1.f - p[4 + c]);
            }
        }
#pragma unroll
        for (int i = 0; i < 32; i++) sT[(16 + i) * RS + col] = lo[i];
    }

    // block-reduce commit & entropy (deterministic shuffle tree; 4 warps)
#pragma unroll
    for (int o = 16; o; o >>= 1) {
        commit += __shfl_down_sync(0xffffffffu, commit, o);
        ent    += __shfl_down_sync(0xffffffffu, ent, o);
    }
    const int wid = t >> 5, lid = t & 31;
    if (lid == 0) { sRed[wid] = commit; sRed[8 + wid] = ent; }

    __syncthreads();   // tables + sRed ready

    if (t == 0) {
        float c = 0.f, e = 0.f;
#pragma unroll
        for (int w = 0; w < 4; w++) { c += sRed[w]; e += sRed[8 + w]; }
        g_pcommit[blk] = c;
        g_pent[blk]    = e;
    }

    // ---- Phase 2: AVG[g][i][j] = sum_px hi[g][px][i]*lo[g][px][j]
    // 4x4 register tile; 8 LDS.128 -> 32 fma2 per 4-px chunk.
    // 128 threads = 64 output tiles x 2 px-subsets of 32 px.
    const int s2  = t >> 6;                // px subset 0..1
    const int u   = t & 63;
    const int gg  = u >> 5;                // warp-uniform
    const int tr  = (u >> 3) & 3;          // == lid>>3 (quarter-warp uniform)
    const int tc  = u & 7;                 // == lid&7
    {
        const float* pH = sT + tr        * RS + gg * GOFF;   // hi rows tr+4k
        const float* pL = sT + (16 + tc) * RS + gg * GOFF;   // lo rows 16+tc+8k

        unsigned long long acc[4][4];
#pragma unroll
        for (int k1 = 0; k1 < 4; k1++)
#pragma unroll
            for (int k2 = 0; k2 < 4; k2++) acc[k1][k2] = 0ull;

        const int px0 = s2 * 32;
#pragma unroll 2
        for (int px = px0; px < px0 + 32; px += 4) {
            ulonglong2 h[4], l[4];
#pragma unroll
            for (int k = 0; k < 4; k++) h[k] = *(const ulonglong2*)(pH + (4 * k) * RS + px);
#pragma unroll
            for (int k = 0; k < 4; k++) l[k] = *(const ulonglong2*)(pL + (8 * k) * RS + px);
#pragma unroll
            for (int k1 = 0; k1 < 4; k1++)
#pragma unroll
                for (int k2 = 0; k2 < 4; k2++) {
                    fma2(acc[k1][k2], h[k1].x, l[k2].x);
                    fma2(acc[k1][k2], h[k1].y, l[k2].y);
                }
        }

        __syncthreads();   // all table reads done; safe to overwrite sT

        // stash: skewed stride-20 layout, conflict-free STS.128
        float* st = sT + t * 20;
#pragma unroll
        for (int k1 = 0; k1 < 4; k1++) {
            float4 v = make_float4(hsum2(acc[k1][0]), hsum2(acc[k1][1]),
                                   hsum2(acc[k1][2]), hsum2(acc[k1][3]));
            *(float4*)(st + k1 * 4) = v;
        }
    }
    __syncthreads();

    // combine 2 px-subsets; thread t owns slots 8t..8t+7 (k2 fixed, tc=m)
    {
        const int slot0 = 8 * t;
        const int g2  = slot0 >> 9;
        const int d   = slot0 & 511;
        const int i   = d >> 5;
        const int j0  = d & 31;              // multiple of 8
        const int k1  = i >> 2;
        const int trr = i & 3;
        const int k2  = j0 >> 3;
        const int e   = k1 * 4 + k2;
        float res[8];
#pragma unroll
        for (int m = 0; m < 8; m++) {
            const int uw = g2 * 32 + trr * 8 + m;
            res[m] = sT[uw * 20 + e] + sT[(64 + uw) * 20 + e];
        }
        float* gp = g_pavg + (size_t)blk * 1024 + slot0;
        *(float4*)(gp)     = make_float4(res[0], res[1], res[2], res[3]);
        *(float4*)(gp + 4) = make_float4(res[4], res[5], res[6], res[7]);
    }
}

// Tail: 256 blocks; block k reduces ALL 1024 partials for slots 4k..4k+3
// in one shot (4 float4 loads/thread -> fixed shuffle+smem tree). g_red then
// holds the final 1024 sums; the last-arriving block finalizes.
__global__ void __launch_bounds__(256) bsq_tail(float* __restrict__ out) {
    __shared__ float4 sq[8];
    __shared__ float sr[24];
    __shared__ int sLast;
    const int t   = threadIdx.x;
    const int k   = blockIdx.x;          // 0..255, owns slots 4k..4k+3
    const int wid = t >> 5, lid = t & 31;

    // stage 1: one-shot load of 4 partial-quads, fixed-order tree reduce
    {
        float4 v = make_float4(0.f, 0.f, 0.f, 0.f);
#pragma unroll
        for (int q = 0; q < 4; q++) {
            float4 a = *(const float4*)(g_pavg + (size_t)(4 * t + q) * 1024 + 4 * k);
            v.x += a.x; v.y += a.y; v.z += a.z; v.w += a.w;
        }
#pragma unroll
        for (int o = 16; o; o >>= 1) {
            v.x += __shfl_down_sync(0xffffffffu, v.x, o);
            v.y += __shfl_down_sync(0xffffffffu, v.y, o);
            v.z += __shfl_down_sync(0xffffffffu, v.z, o);
            v.w += __shfl_down_sync(0xffffffffu, v.w, o);
        }
        if (lid == 0) sq[wid] = v;
    }
    __syncthreads();
    if (t == 0) {
        float4 s = sq[0];
#pragma unroll
        for (int w = 1; w < 8; w++) {
            s.x += sq[w].x; s.y += sq[w].y; s.z += sq[w].z; s.w += sq[w].w;
        }
        *(float4*)(g_red + 4 * k) = s;
    }
    __threadfence();
    if (t == 0) {
        int v = atomicAdd(&g_cnt, 1);
        sLast = (v == NTAIL - 1);
    }
    __syncthreads();
    if (!sLast) return;

    // stage 2 (last block): finalize from the 1024 final sums
    if (t == 0) g_cnt = 0;               // reset for next graph replay
    float4 s = *(const float4*)(g_red + 4 * t);
    const float inv = 1.f / (float)NPIX;
    float4 avg = make_float4(s.x * inv, s.y * inv, s.z * inv, s.w * inv);
    // avg_prob region is 8B-aligned only -> float2 stores
    *(float2*)(out + OFF_AVGP + 4 * t)     = make_float2(avg.x, avg.y);
    *(float2*)(out + OFF_AVGP + 4 * t + 2) = make_float2(avg.z, avg.w);
    float cterm = -avg.x * __logf(avg.x + 1e-8f)
                - avg.y * __logf(avg.y + 1e-8f)
                - avg.z * __logf(avg.z + 1e-8f)
                - avg.w * __logf(avg.w + 1e-8f);
    // commit/entropy over 1024 block-partials: thread t handles t+256m
    float cm = 0.f, en = 0.f;
#pragma unroll
    for (int m = 0; m < 4; m++) {
        cm += g_pcommit[t + 256 * m];
        en += g_pent[t + 256 * m];
    }
#pragma unroll
    for (int o = 16; o; o >>= 1) {
        cterm += __shfl_down_sync(0xffffffffu, cterm, o);
        cm    += __shfl_down_sync(0xffffffffu, cm, o);
        en    += __shfl_down_sync(0xffffffffu, en, o);
    }
    if (lid == 0) { sr[wid] = cterm; sr[8 + wid] = cm; sr[16 + wid] = en; }
    __syncthreads();
    if (t == 0) {
        float cbE = 0.f, cmS = 0.f, enS = 0.f;
#pragma unroll
        for (int w = 0; w < 8; w++) {
            cbE += sr[w]; cmS += sr[8 + w]; enS += sr[16 + w];
        }
        float commit_loss = 0.25f * cmS * (1.f / (float)NPIX);
        float pse = enS * (1.f / (float)NPIX);
        out[OFF_LOSS] = commit_loss + pse - cbE;   // GAMMA0=GAMMA=ZETA=INV_T=1
        out[OFF_CBE]  = cbE;
    }
}

extern "C" void kernel_launch(void* const* d_in, const int* in_sizes, int n_in,
                              void* d_out, int out_size) {
    const float* z = (const float*)d_in[0];
    float* out = (float*)d_out;

    const size_t smem = SMEM_FLOATS * sizeof(float);   // 31,744 B
    cudaFuncSetAttribute(bsq_main, cudaFuncAttributeMaxDynamicSharedMemorySize, 48 * 1024);

    bsq_main<<<NBLK, NTHR, smem>>>(z, out);
    bsq_tail<<<NTAIL, 256>>>(out);
}

// round 16
// speedup vs baseline: 1.0603x; 1.0603x over previous
#include <cuda_runtime.h>
#include <math.h>

// Problem constants
#define NPIX   65536        // B*H*W = 16*64*64
#define HW     4096         // 64*64
#define TILE   128          // pixels per block
#define NBLK   (NPIX/TILE)  // 512
#define NTHR   256
#define NTAIL  256          // tail blocks (one per 4 codebook slots)

// Transposed table layout: sT[row*RS + g*GOFF + pix]
#define RS    292
#define GOFF  144
#define SRED_OFF (48 * RS)       // 14016
#define SMEM_FLOATS (SRED_OFF + 64)

// Output layout (flattened tuple, float32):
// zq[16,18,64,64] | loss | cb_entropy | indices[16,64,64] | group_indices[16,64,64,2] | avg_prob[2,512]
#define OFF_ZQ    0
#define OFF_LOSS  1179648
#define OFF_CBE   1179649
#define OFF_IDX   1179650
#define OFF_GIDX  1245186
#define OFF_AVGP  1376258   // byte addr mod 16 == 8 -> max 8B-wide stores here!

// Deterministic per-block partials; fixed-order reduction trees throughout.
__device__ __align__(16) float g_pavg[NBLK * 1024];
__device__ __align__(16) float g_red[1024];
__device__ float g_pcommit[NBLK];
__device__ float g_pent[NBLK];
__device__ int   g_cnt;          // zero-init; self-resetting each launch

__device__ __forceinline__ void fma2(unsigned long long& acc,
                                     unsigned long long a, unsigned long long b) {
    asm("fma.rn.f32x2 %0, %1, %2, %0;" : "+l"(acc) : "l"(a), "l"(b));
}
__device__ __forceinline__ float hsum2(unsigned long long acc) {
    float lo, hi;
    asm("mov.b64 {%0, %1}, %2;" : "=f"(lo), "=f"(hi) : "l"(acc));
    return lo + hi;
}
// FFMA-only reciprocal of x in (1,2]: minimax seed + 2 Newton (rel err ~1e-5).
// Moves work off the saturated MUFU pipe onto the underused FMA pipe.
__device__ __forceinline__ float rcp_newton(float x) {
    float y = fmaf(x, -0.470588235f, 1.411764706f);   // 24/17 - 8/17 x
    y = y * fmaf(-x, y, 2.f);
    y = y * fmaf(-x, y, 2.f);
    return y;
}

__global__ void __launch_bounds__(NTHR) bsq_main(const float* __restrict__ z,
                                                 float* __restrict__ out) {
    extern __shared__ float sT[];
    float* sRed = sT + SRED_OFF;

    const int t   = threadIdx.x;
    const int blk = blockIdx.x;
    const int pix = t >> 1;                  // 0..127
    const int g   = t & 1;                   // group 0/1
    const int P   = blk * TILE + pix;        // global pixel
    const int b   = P >> 12;                 // batch
    const int hw  = P & 4095;

    const float* zp  = z   + (size_t)(b * 18 + g * 9) * HW + hw;
    float*       zqp = out + OFF_ZQ + (size_t)(b * 18 + g * 9) * HW + hw;

    // ---- Phase 1: per-(pixel,group) work ----
    // ent = ln( prod_j (1+E_j) ) + sum_j q_j*a_j,  E=e^{-4|v|}, q=E/(1+E)
    // q via FFMA-Newton reciprocal (no MUFU); tables built UNNORMALIZED from
    // E_j (u=1 match / u=E mismatch) with the single scale S=1/prod(1+E)
    // folded into the hi-table seeds. 11 MUFU/thread instead of 19.
    float E[9];
    unsigned gidx = 0;
    float commit = 0.f, qa = 0.f, prodE = 1.f;
#pragma unroll
    for (int j = 0; j < 9; j++) {
        float v = zp[j * HW];
        bool s = v > 0.f;
        gidx = (gidx << 1) | (unsigned)s;
        float zh = s ? 1.f : -1.f;
        zqp[j * HW] = zh;                    // zq forward value == sign(z)
        float d = zh - v;
        commit += d * d;
        float a = 4.f * fabsf(v);
        float Ej = __expf(-a);
        E[j] = Ej;
        float x = 1.f + Ej;
        prodE *= x;
        float y = rcp_newton(x);             // ~1/(1+E), FFMA-only
        qa += (Ej * y) * a;                  // q_j * a_j
    }
    float ent = __logf(prodE) + qa;
    float S = __fdividef(1.f, prodE);        // table normalizer

    // indices: pair of threads (g=0,g=1) are adjacent lanes
    unsigned other = __shfl_xor_sync(0xffffffffu, gidx, 1);
    out[OFF_GIDX + (size_t)P * 2 + g] = (float)gidx;
    if (g == 0)
        out[OFF_IDX + P] = (float)(gidx * 512u + other);

    // build hi[16]/lo[32] in regs (u-form), write transposed (conflict-free STS)
    // channel c sign: bit (8-c) of gidx. u(bit=1)= s?1:E ; u(bit=0)= s?E:1.
    const int col = g * GOFF + pix;
    {
        float hi[16];
        {
            bool s0 = (gidx >> 8) & 1u;
            hi[0] = s0 ? E[0] * S : S;       // f0_0 * S
            hi[1] = s0 ? S : E[0] * S;       // f1_0 * S
        }
#pragma unroll
        for (int c = 1; c < 4; c++) {
            bool sc = (gidx >> (8 - c)) & 1u;
            float f1 = sc ? 1.f : E[c];
            float f0 = sc ? E[c] : 1.f;
            const int n = 1 << c;
#pragma unroll
            for (int i = n - 1; i >= 0; i--) {
                float v = hi[i];
                hi[2 * i + 1] = v * f1;
                hi[2 * i]     = v * f0;
            }
        }
#pragma unroll
        for (int i = 0; i < 16; i++) sT[i * RS + col] = hi[i];
    }
    {
        float lo[32];
        {
            bool s4 = (gidx >> 4) & 1u;
            lo[0] = s4 ? E[4] : 1.f;
            lo[1] = s4 ? 1.f : E[4];
        }
#pragma unroll
        for (int c = 1; c < 5; c++) {
            bool sc = (gidx >> (4 - c)) & 1u;
            float f1 = sc ? 1.f : E[4 + c];
            float f0 = sc ? E[4 + c] : 1.f;
            const int n = 1 << c;
#pragma unroll
            for (int i = n - 1; i >= 0; i--) {
                float v = lo[i];
                lo[2 * i + 1] = v * f1;
                lo[2 * i]     = v * f0;
            }
        }
#pragma unroll
        for (int i = 0; i < 32; i++) sT[(16 + i) * RS + col] = lo[i];
    }

    // block-reduce commit & entropy (deterministic shuffle tree)
#pragma unroll
    for (int o = 16; o; o >>= 1) {
        commit += __shfl_down_sync(0xffffffffu, commit, o);
        ent    += __shfl_down_sync(0xffffffffu, ent, o);
    }
    const int wid = t >> 5, lid = t & 31;
    if (lid == 0) { sRed[wid] = commit; sRed[8 + wid] = ent; }

    __syncthreads();   // tables + sRed ready

    if (t == 0) {
        float c = 0.f, e = 0.f;
#pragma unroll
        for (int w = 0; w < 8; w++) { c += sRed[w]; e += sRed[8 + w]; }
        g_pcommit[blk] = c;
        g_pent[blk]    = e;
    }

    // ---- Phase 2: AVG[g][i][j] = sum_px hi[g][px][i]*lo[g][px][j]
    // 4x4 register tile; 8 LDS.128 -> 32 fma2 per 4-px chunk.
    const int s2  = t >> 6;                // px subset 0..3
    const int u   = t & 63;
    const int gg  = u >> 5;
    const int tr  = (u >> 3) & 3;          // quarter-warp uniform
    const int tc  = u & 7;
    {
        const float* pH = sT + tr        * RS + gg * GOFF;   // hi rows tr+4k
        const float* pL = sT + (16 + tc) * RS + gg * GOFF;   // lo rows 16+tc+8k

        unsigned long long acc[4][4];
#pragma unroll
        for (int k1 = 0; k1 < 4; k1++)
#pragma unroll
            for (int k2 = 0; k2 < 4; k2++) acc[k1][k2] = 0ull;

        const int px0 = s2 * 32;
#pragma unroll 2
        for (int px = px0; px < px0 + 32; px += 4) {
            ulonglong2 h[4], l[4];
#pragma unroll
            for (int k = 0; k < 4; k++) h[k] = *(const ulonglong2*)(pH + (4 * k) * RS + px);
#pragma unroll
            for (int k = 0; k < 4; k++) l[k] = *(const ulonglong2*)(pL + (8 * k) * RS + px);
#pragma unroll
            for (int k1 = 0; k1 < 4; k1++)
#pragma unroll
                for (int k2 = 0; k2 < 4; k2++) {
                    fma2(acc[k1][k2], h[k1].x, l[k2].x);
                    fma2(acc[k1][k2], h[k1].y, l[k2].y);
                }
        }

        __syncthreads();   // all table reads done; safe to overwrite sT

        // stash: skewed stride-20 layout, conflict-free STS.128
        float* st = sT + t * 20;
#pragma unroll
        for (int k1 = 0; k1 < 4; k1++) {
            float4 v = make_float4(hsum2(acc[k1][0]), hsum2(acc[k1][1]),
                                   hsum2(acc[k1][2]), hsum2(acc[k1][3]));
            *(float4*)(st + k1 * 4) = v;
        }
    }
    __syncthreads();

    // combine 4 px-subsets; thread t owns slots 4t..4t+3
    {
        const int slot0 = 4 * t;
        const int ggr = slot0 >> 9;
        const int d   = slot0 & 511;
        const int i   = d >> 5;
        const int j0  = d & 31;              // multiple of 4
        const int k1  = i >> 2;
        const int trr = i & 3;
        const int k2  = j0 >> 3;
        const int e   = k1 * 4 + k2;
        float res[4];
#pragma unroll
        for (int m = 0; m < 4; m++) {
            const int tcc = (j0 & 7) + m;
            const int uw  = ggr * 32 + trr * 8 + tcc;
            float v = 0.f;
#pragma unroll
            for (int q = 0; q < 4; q++)
                v += sT[(q * 64 + uw) * 20 + e];
            res[m] = v;
        }
        *(float4*)(g_pavg + (size_t)blk * 1024 + slot0) =
            make_float4(res[0], res[1], res[2], res[3]);
    }
}

// Tail: 256 blocks; block k reduces ALL 512 partials for slots 4k..4k+3
// in one shot (2 float4 loads/thread -> fixed shuffle+smem tree). g_red then
// holds the final 1024 sums; the last-arriving block finalizes.
__global__ void __launch_bounds__(256) bsq_tail(float* __restrict__ out) {
    __shared__ float4 sq[8];
    __shared__ float sr[24];
    __shared__ int sLast;
    const int t   = threadIdx.x;
    const int k   = blockIdx.x;          // 0..255, owns slots 4k..4k+3
    const int wid = t >> 5, lid = t & 31;

    // stage 1: one-shot load of 2 partial-quads, fixed-order tree reduce
    {
        float4 a = *(const float4*)(g_pavg + (size_t)(2 * t)     * 1024 + 4 * k);
        float4 b = *(const float4*)(g_pavg + (size_t)(2 * t + 1) * 1024 + 4 * k);
        float4 v = make_float4(a.x + b.x, a.y + b.y, a.z + b.z, a.w + b.w);
#pragma unroll
        for (int o = 16; o; o >>= 1) {
            v.x += __shfl_down_sync(0xffffffffu, v.x, o);
            v.y += __shfl_down_sync(0xffffffffu, v.y, o);
            v.z += __shfl_down_sync(0xffffffffu, v.z, o);
            v.w += __shfl_down_sync(0xffffffffu, v.w, o);
        }
        if (lid == 0) sq[wid] = v;
    }
    __syncthreads();
    if (t == 0) {
        float4 s = sq[0];
#pragma unroll
        for (int w = 1; w < 8; w++) {
            s.x += sq[w].x; s.y += sq[w].y; s.z += sq[w].z; s.w += sq[w].w;
        }
        *(float4*)(g_red + 4 * k) = s;
    }
    __threadfence();
    if (t == 0) {
        int v = atomicAdd(&g_cnt, 1);
        sLast = (v == NTAIL - 1);
    }
    __syncthreads();
    if (!sLast) return;

    // stage 2 (last block): finalize from the 1024 final sums
    if (t == 0) g_cnt = 0;               // reset for next graph replay
    float4 s = *(const float4*)(g_red + 4 * t);
    const float inv = 1.f / (float)NPIX;
    float4 avg = make_float4(s.x * inv, s.y * inv, s.z * inv, s.w * inv);
    // avg_prob region is 8B-aligned only -> float2 stores
    *(float2*)(out + OFF_AVGP + 4 * t)     = make_float2(avg.x, avg.y);
    *(float2*)(out + OFF_AVGP + 4 * t + 2) = make_float2(avg.z, avg.w);
    float cterm = -avg.x * __logf(avg.x + 1e-8f)
                - avg.y * __logf(avg.y + 1e-8f)
                - avg.z * __logf(avg.z + 1e-8f)
                - avg.w * __logf(avg.w + 1e-8f);
    float cm = g_pcommit[t] + g_pcommit[t + 256];
    float en = g_pent[t]    + g_pent[t + 256];
#pragma unroll
    for (int o = 16; o; o >>= 1) {
        cterm += __shfl_down_sync(0xffffffffu, cterm, o);
        cm    += __shfl_down_sync(0xffffffffu, cm, o);
        en    += __shfl_down_sync(0xffffffffu, en, o);
    }
    if (lid == 0) { sr[wid] = cterm; sr[8 + wid] = cm; sr[16 + wid] = en; }
    __syncthreads();
    if (t == 0) {
        float cbE = 0.f, cmS = 0.f, enS = 0.f;
#pragma unroll
        for (int w = 0; w < 8; w++) {
            cbE += sr[w]; cmS += sr[8 + w]; enS += sr[16 + w];
        }
        float commit_loss = 0.25f * cmS * (1.f / (float)NPIX);
        float pse = enS * (1.f / (float)NPIX);
        out[OFF_LOSS] = commit_loss + pse - cbE;   // GAMMA0=GAMMA=ZETA=INV_T=1
        out[OFF_CBE]  = cbE;
    }
}

extern "C" void kernel_launch(void* const* d_in, const int* in_sizes, int n_in,
                              void* d_out, int out_size) {
    const float* z = (const float*)d_in[0];
    float* out = (float*)d_out;

    const size_t smem = SMEM_FLOATS * sizeof(float);   // 56,320 B
    cudaFuncSetAttribute(bsq_main, cudaFuncAttributeMaxDynamicSharedMemorySize, 64 * 1024);

    bsq_main<<<NBLK, NTHR, smem>>>(z, out);
    bsq_tail<<<NTAIL, 256>>>(out);
}